// round 6
// baseline (speedup 1.0000x reference)
#include <cuda_runtime.h>
#include <cuda_bf16.h>
#include <math.h>

// ---------------------------------------------------------------------------
// SRNN ALIF — bit-exact-vs-XLA-CPU fp32 strategy.
// GEMMs: serial ascending-k fp32 FMA chain per output (== Eigen gebp, kc>=K).
// Elementwise: explicit non-contracted fp32 ops (XLA HLO per-op rounding).
// exp: XLA:CPU's inlined Cephes polynomial (GenerateVF32Exp / Eigen pexp),
//      with FMA (NEON pmadd), NOT libm expf.
// ---------------------------------------------------------------------------

#define T_STEPS 100
#define NBATCH  64
#define HID     512
#define INSZ    1024

__device__ float d_xp  [2 * T_STEPS * NBATCH * INSZ];   // pooled [c][t][n][1024]
__device__ float d_in12[2 * T_STEPS * NBATCH * HID];    // ff proj [c][t][n][512]
__device__ float d_s12 [T_STEPS * NBATCH * INSZ];       // spikes s1||s2 [t][n][1024]
__device__ float d_ff3 [T_STEPS * NBATCH * HID];        // concat@W1 (+b1) [t][n][512]
__device__ float d_wt  [HID * HID];                     // w_h2h3 transposed [j][i]

// ---------------------------------------------------------------------------
// XLA:CPU exp — Cephes/Eigen pexp<float> with FMA, exact op order.
// ---------------------------------------------------------------------------
__device__ __forceinline__ float xla_expf(float x) {
    const float exp_hi = 88.723164f, exp_lo = -88.723164f;
    x = fminf(fmaxf(x, exp_lo), exp_hi);
    float m = floorf(__fmaf_rn(x, 1.44269504088896341f, 0.5f));
    float r = __fmaf_rn(m, -0.693359375f, x);        // r = x - m*ln2_hi
    r = __fmaf_rn(m, 2.12194440e-4f, r);             // r -= m*ln2_lo (ln2_lo<0)
    float r2 = __fmul_rn(r, r);
    float y = 1.9875691500e-4f;
    y = __fmaf_rn(y, r, 1.3981999507e-3f);
    y = __fmaf_rn(y, r, 8.3334519073e-3f);
    y = __fmaf_rn(y, r, 4.1665795894e-2f);
    y = __fmaf_rn(y, r, 1.6666665459e-1f);
    y = __fmaf_rn(y, r, 5.0000001201e-1f);
    y = __fmaf_rn(y, r2, r);
    y = __fadd_rn(y, 1.0f);
    return ldexpf(y, (int)m);                        // m==0 for our inputs
}

__device__ __forceinline__ float alpha_of(float tau) {
    return xla_expf(__fdiv_rn(-1.0f, tau));          // divide.rn + XLA exp
}

// ---------------------------------------------------------------------------
// 1) maxpool 4x4 stride 4 (exact): x[n][t][c][128][128] -> xp[c][t][n][1024]
// ---------------------------------------------------------------------------
__global__ void pool_kernel(const float* __restrict__ x) {
    int tid = blockIdx.x * blockDim.x + threadIdx.x;   // 13,107,200 threads
    int i    = tid & 1023;
    int n    = (tid >> 10) & 63;
    int rest = tid >> 16;          // c*100 + t
    int t    = rest % 100;
    int c    = rest / 100;
    int ph = i >> 5, pw = i & 31;
    const float* base = x + (((size_t)(n * 100 + t) * 2 + c) << 14) + ph * 512 + pw * 4;
    float mx = -3.4e38f;
#pragma unroll
    for (int r = 0; r < 4; r++) {
        float4 v = *(const float4*)(base + r * 128);
        mx = fmaxf(mx, fmaxf(fmaxf(v.x, v.y), fmaxf(v.z, v.w)));
    }
    d_xp[tid] = mx;
}

// ---------------------------------------------------------------------------
// 2) fp32 GEMM (NT), serial ascending-k FFMA per output:
//    C[6400][512] = A[6400][1024] * W[512][1024]^T + bias
// ---------------------------------------------------------------------------
#define BM 128
#define BN 64
#define BK 16
__global__ __launch_bounds__(256)
void gemm_nt(const float* __restrict__ A, const float* __restrict__ W,
             const float* __restrict__ bias_a, float* __restrict__ C) {
    __shared__ float As[BK][BM];
    __shared__ float Ws[BK][BN];
    int tid = threadIdx.x;
    int rowBase = blockIdx.y * BM;
    int colBase = blockIdx.x * BN;
    int tx = tid & 15;    // cols tx*4..+3
    int ty = tid >> 4;    // rows ty*8..+7
    float acc[8][4];
#pragma unroll
    for (int r = 0; r < 8; r++)
#pragma unroll
        for (int cI = 0; cI < 4; cI++) acc[r][cI] = 0.f;

    for (int k0 = 0; k0 < 1024; k0 += BK) {
        __syncthreads();
#pragma unroll
        for (int u = 0; u < 2; u++) {
            int slot = tid * 2 + u;           // 512 float4 slots
            int m = slot >> 2, kq = slot & 3;
            float4 v = *(const float4*)&A[(size_t)(rowBase + m) * 1024 + k0 + kq * 4];
            As[kq * 4 + 0][m] = v.x; As[kq * 4 + 1][m] = v.y;
            As[kq * 4 + 2][m] = v.z; As[kq * 4 + 3][m] = v.w;
        }
        {
            int nn = tid >> 2, kq = tid & 3;  // 256 float4 slots
            float4 v = *(const float4*)&W[(size_t)(colBase + nn) * 1024 + k0 + kq * 4];
            Ws[kq * 4 + 0][nn] = v.x; Ws[kq * 4 + 1][nn] = v.y;
            Ws[kq * 4 + 2][nn] = v.z; Ws[kq * 4 + 3][nn] = v.w;
        }
        __syncthreads();
        // strict ascending k accumulation, one accumulator per output
#pragma unroll
        for (int k = 0; k < BK; k++) {
            float a[8], w[4];
#pragma unroll
            for (int r = 0; r < 8; r++) a[r] = As[k][ty * 8 + r];
#pragma unroll
            for (int cI = 0; cI < 4; cI++) w[cI] = Ws[k][tx * 4 + cI];
#pragma unroll
            for (int r = 0; r < 8; r++)
#pragma unroll
                for (int cI = 0; cI < 4; cI++)
                    acc[r][cI] = __fmaf_rn(a[r], w[cI], acc[r][cI]);
        }
    }
    float badd[4];
#pragma unroll
    for (int cI = 0; cI < 4; cI++)
        badd[cI] = bias_a ? bias_a[colBase + tx * 4 + cI] : 0.f;   // zeros in practice
#pragma unroll
    for (int r = 0; r < 8; r++) {
        size_t rowOff = (size_t)(rowBase + ty * 8 + r) * 512 + colBase + tx * 4;
#pragma unroll
        for (int cI = 0; cI < 4; cI++)
            C[rowOff + cI] = __fadd_rn(acc[r][cI], badd[cI]);
    }
}

// ---------------------------------------------------------------------------
// ALIF update: XLA HLO op-for-op — every op individually rounded, no FMA.
// ---------------------------------------------------------------------------
__device__ __forceinline__ void alif(float inp, float& m, float& s, float& bb,
                                     float alpha, float omAlpha, float ro, float omRo) {
    bb = __fadd_rn(__fmul_rn(ro, bb), __fmul_rn(omRo, s));
    float B = __fadd_rn(0.1f, __fmul_rn(1.8f, bb));
    float t1 = __fadd_rn(__fmul_rn(m, alpha), __fmul_rn(omAlpha, inp));
    m = __fsub_rn(t1, __fmul_rn(B, s));
    s = (__fsub_rn(m, B) > 0.f) ? 1.f : 0.f;
}

// ---------------------------------------------------------------------------
// 3) Layers 1 & 2 scans — fully parallel per neuron (no recurrent weights)
// ---------------------------------------------------------------------------
__global__ void scan12_kernel(const float* __restrict__ tau_adp1, const float* __restrict__ tau_adp2,
                              const float* __restrict__ tau_m1,  const float* __restrict__ tau_m2) {
    int tid = blockIdx.x * blockDim.x + threadIdx.x;   // 65536
    int h = tid & 511;
    int n = (tid >> 9) & 63;
    int layer = tid >> 15;
    float alpha = alpha_of(layer ? tau_m2[h]   : tau_m1[h]);
    float ro    = alpha_of(layer ? tau_adp2[h] : tau_adp1[h]);
    float omA = __fsub_rn(1.0f, alpha);
    float omR = __fsub_rn(1.0f, ro);
    float m = 0.f, bb = 0.1f, s = 0.f;
    const float* inbase = d_in12 + (size_t)layer * T_STEPS * NBATCH * HID;
    for (int t = 0; t < T_STEPS; t++) {
        float inp = inbase[((size_t)t * NBATCH + n) * HID + h];
        alif(inp, m, s, bb, alpha, omA, ro, omR);
        d_s12[((size_t)t * NBATCH + n) * INSZ + layer * HID + h] = s;
    }
}

// ---------------------------------------------------------------------------
// 4) transpose w_h2h3 [512][512] -> wt[j][i]  (pure copy, exact)
// ---------------------------------------------------------------------------
__global__ void transpose512(const float* __restrict__ w) {
    __shared__ float tile[32][33];
    int bx = blockIdx.x * 32, by = blockIdx.y * 32;
#pragma unroll
    for (int r = 0; r < 4; r++)
        tile[threadIdx.y + 8 * r][threadIdx.x] = w[(size_t)(by + threadIdx.y + 8 * r) * 512 + bx + threadIdx.x];
    __syncthreads();
#pragma unroll
    for (int r = 0; r < 4; r++)
        d_wt[(size_t)(bx + threadIdx.y + 8 * r) * 512 + by + threadIdx.x] =
            tile[threadIdx.x][threadIdx.y + 8 * r];
}

// ---------------------------------------------------------------------------
// 5) Layer-3 sequential scan. One CTA/batch, one thread/neuron.
//    recur_i = single serial ascending-j fp32 add chain over ACTIVE j
//    (bit-identical to the dense ascending FFMA chain with s in {0,1}).
// ---------------------------------------------------------------------------
__global__ __launch_bounds__(512)
void layer3_kernel(const float* __restrict__ w_h2o3, const float* __restrict__ b_h2o3,
                   const float* __restrict__ b_h2h3,
                   const float* __restrict__ tau_adp, const float* __restrict__ tau_m,
                   float* __restrict__ out) {
    int n = blockIdx.x;      // batch
    int i = threadIdx.x;     // neuron
    __shared__ int   list[512];
    __shared__ int   warpcnt[16];
    __shared__ float s3sm[512];

    float alpha = alpha_of(tau_m[i]);
    float ro    = alpha_of(tau_adp[i]);
    float omA = __fsub_rn(1.0f, alpha);
    float omR = __fsub_rn(1.0f, ro);
    float b2  = b_h2h3[i];   // zero in practice
    float m = 0.f, bb = 0.1f, s = 0.f;
    int wid = i >> 5, lane = i & 31;
    unsigned lanemask = (1u << lane) - 1u;

    for (int t = 0; t < T_STEPS; t++) {
        __syncthreads();  // previous iteration's gather done before list rewrite
        unsigned mask = __ballot_sync(0xffffffffu, s != 0.f);
        if (lane == 0) warpcnt[wid] = __popc(mask);
        __syncthreads();
        int off = 0, total = 0;
#pragma unroll
        for (int w = 0; w < 16; w++) { int c = warpcnt[w]; total += c; if (w < wid) off += c; }
        if (s != 0.f) list[off + __popc(mask & lanemask)] = i;   // ascending j order
        __syncthreads();

        // single-accumulator serial chain, ascending j — bit-exact vs dense FFMA
        float recur = 0.f;
#pragma unroll 4
        for (int k = 0; k < total; k++)
            recur = __fadd_rn(recur, d_wt[(size_t)list[k] * 512 + i]);

        float ffv = d_ff3[((size_t)t * NBATCH + n) * HID + i];   // concat@W1 + b1
        float inp = __fadd_rn(__fadd_rn(ffv, recur), b2);        // ((..)+recur)+b2
        alif(inp, m, s, bb, alpha, omA, ro, omR);
    }
    s3sm[i] = s;
    __syncthreads();
    if (i < 11) {
        float acc = 0.f;
        for (int j = 0; j < 512; j++)
            acc = __fmaf_rn(s3sm[j], w_h2o3[(size_t)i * 512 + j], acc);
        out[n * 11 + i] = __fadd_rn(acc, b_h2o3[i]);
    }
}

// ---------------------------------------------------------------------------
extern "C" void kernel_launch(void* const* d_in, const int* in_sizes, int n_in,
                              void* d_out, int out_size) {
    const float* x          = (const float*)d_in[0];
    const float* w_i2h1     = (const float*)d_in[1];
    const float* b_i2h1     = (const float*)d_in[2];
    const float* w_i2h2     = (const float*)d_in[3];
    const float* b_i2h2     = (const float*)d_in[4];
    const float* w_i2h3     = (const float*)d_in[5];
    const float* b_i2h3     = (const float*)d_in[6];
    const float* w_h2h3     = (const float*)d_in[7];
    const float* b_h2h3     = (const float*)d_in[8];
    const float* w_h2o3     = (const float*)d_in[9];
    const float* b_h2o3     = (const float*)d_in[10];
    const float* tau_adp_h1 = (const float*)d_in[11];
    const float* tau_adp_h2 = (const float*)d_in[12];
    const float* tau_adp_h3 = (const float*)d_in[13];
    const float* tau_m_h1   = (const float*)d_in[14];
    const float* tau_m_h2   = (const float*)d_in[15];
    const float* tau_m_h3   = (const float*)d_in[16];
    float* out = (float*)d_out;

    float *xp, *in12, *s12, *ff3;
    cudaGetSymbolAddress((void**)&xp,   d_xp);
    cudaGetSymbolAddress((void**)&in12, d_in12);
    cudaGetSymbolAddress((void**)&s12,  d_s12);
    cudaGetSymbolAddress((void**)&ff3,  d_ff3);

    pool_kernel<<<51200, 256>>>(x);

    dim3 ggrid(512 / BN, 6400 / BM);
    gemm_nt<<<ggrid, 256>>>(xp,                                   w_i2h1, b_i2h1, in12);
    gemm_nt<<<ggrid, 256>>>(xp + (size_t)T_STEPS * NBATCH * INSZ, w_i2h2, b_i2h2,
                            in12 + (size_t)T_STEPS * NBATCH * HID);

    scan12_kernel<<<256, 256>>>(tau_adp_h1, tau_adp_h2, tau_m_h1, tau_m_h2);

    transpose512<<<dim3(16, 16), dim3(32, 8)>>>(w_h2h3);

    gemm_nt<<<ggrid, 256>>>(s12, w_i2h3, b_i2h3, ff3);

    layer3_kernel<<<NBATCH, 512>>>(w_h2o3, b_h2o3, b_h2h3, tau_adp_h3, tau_m_h3, out);
}